// round 5
// baseline (speedup 1.0000x reference)
#include <cuda_runtime.h>
#include <cstdint>

// ---------------- constants ----------------
#define CHUNK   1024
#define MAXN    262144
#define MAXCH   256
#define NBPAD   4352
#define IDXBITS 21
#define IDXMASK ((1u<<IDXBITS)-1u)
#define RAD2    2.25f
#define MINBETA 0.8f

#define GD      11
#define GHALF   8.25f
#define CINV    0.666f
#define GCELLS  (2*GD*GD*GD)    // 2662
#define MAXCG   2048

// ---------------- device scratch ----------------
static __device__ uint64_t g_keyA[MAXN];
static __device__ uint64_t g_keyB[MAXN];
static __device__ int      g_hist [MAXCH * NBPAD];
static __device__ int      g_hist2[MAXCH * NBPAD];
static __device__ int      g_dense[NBPAD];
static __device__ int      g_ccnt[MAXCH];
static __device__ int      g_coff[MAXCH];
static __device__ int      g_done;
static __device__ float4   g_cp[MAXCG];
static __device__ int      g_headG[GCELLS];
static __device__ int      g_nxtG[MAXCG];
static __device__ int      g_cpid2bin[MAXCG];
static __device__ int      g_g[MAXN];          // final bin per point
static __device__ int      g_pos[MAXN];
static __device__ int      g_M;
static __device__ int      g_nC;

// ---------------- helpers ----------------
__device__ __forceinline__ int blkscan_excl(int v, int tid, int* ws) {
    __syncthreads();
    int lane = tid & 31, w = tid >> 5;
    int inc = v;
    #pragma unroll
    for (int o = 1; o < 32; o <<= 1) {
        int u = __shfl_up_sync(0xffffffffu, inc, o);
        if (lane >= o) inc += u;
    }
    if (lane == 31) ws[w] = inc;
    __syncthreads();
    if (tid < 32) {
        int s = ws[tid];
        #pragma unroll
        for (int o = 1; o < 32; o <<= 1) {
            int u = __shfl_up_sync(0xffffffffu, s, o);
            if (lane >= o) s += u;
        }
        ws[tid] = s;
    }
    __syncthreads();
    return (w ? ws[w - 1] : 0) + inc - v;
}

__device__ __forceinline__ float dist2(float ax, float ay, float az,
                                       float bx, float by, float bz) {
    float dx = ax - bx, dy = ay - by, dz = az - bz;
    return fmaf(dz, dz, fmaf(dy, dy, dx * dx));   // matches XLA fma chain
}

__device__ __forceinline__ int cell1(float v) {
    int c = (int)floorf((v + GHALF) * CINV);
    return c < 0 ? 0 : (c > GD - 1 ? GD - 1 : c);
}
__device__ __forceinline__ int cell_of(float x, float y, float z, int seg) {
    return ((seg * GD + cell1(z)) * GD + cell1(y)) * GD + cell1(x);
}

// stable block rank via warp spin-handoff (no block barriers):
// warps proceed in tid order through a volatile smem token; each warp groups
// equal digits with match_any and bumps a per-digit counter once per group.
__device__ __forceinline__ int stable_rank_spin(int d, bool valid, int tid,
                                                int* cnt, volatile int* turn) {
    int lane = tid & 31, w = tid >> 5;
    int d_eff = valid ? d : (0x10000 + lane);       // invalid lanes: unique singleton groups
    if (lane == 0) while (*turn != w) { }
    __syncwarp();
    unsigned mm = __match_any_sync(0xffffffffu, d_eff);
    int ldr = __ffs(mm) - 1;
    int lower = __popc(mm & ((1u << lane) - 1u));
    int base = 0;
    if (lane == ldr && valid) base = atomicAdd(&cnt[d], __popc(mm));
    base = __shfl_sync(mm, base, ldr);
    __syncwarp();
    __threadfence_block();
    if (lane == 0) *turn = w + 1;
    return base + lower;
}

// ---------------- kernels ----------------
// 1. count candidates per chunk, zero hist buffers, init psrs; last block scans
__global__ __launch_bounds__(1024) void k_candcount(const float* __restrict__ betas, int n,
                                                    float* __restrict__ psrs) {
    int gsz = gridDim.x;
    int tot = MAXCH * NBPAD;
    for (int idx = blockIdx.x * 1024 + threadIdx.x; idx < tot; idx += gsz * 1024) {
        g_hist[idx] = 0; g_hist2[idx] = 0;
    }
    int t = blockIdx.x * 1024 + threadIdx.x;
    if (t <= n) psrs[t] = (float)n;
    int pred = (t < n) && (betas[t] >= MINBETA);
    int cnt = __syncthreads_count(pred);
    if (threadIdx.x == 0) {
        g_ccnt[blockIdx.x] = cnt;
        __threadfence();
        if (atomicAdd(&g_done, 1) == gsz - 1) {
            int s = 0;
            for (int c = 0; c < gsz; c++) { g_coff[c] = s; s += g_ccnt[c]; }
            g_M = s;
            g_done = 0;
        }
    }
}

// 2. compact candidate keys + fused pass-1 histogram
__global__ __launch_bounds__(1024) void k_candscatter(const float* __restrict__ betas, int n) {
    __shared__ int ws[32];
    int tid = threadIdx.x;
    int t = blockIdx.x * 1024 + tid;
    int pred = (t < n) && (betas[t] >= MINBETA);
    int lr = blkscan_excl(pred, tid, ws);
    if (pred) {
        unsigned bits = __float_as_uint(betas[t]);
        uint64_t m = (~bits) & 0x7FFFFFu;
        uint64_t key = (m << IDXBITS) | (unsigned)t;
        int dest = g_coff[blockIdx.x] + lr;
        g_keyA[dest] = key;
        int d = (int)((key >> 21) & 4095u);
        atomicAdd(&g_hist[(dest >> 10) * NBPAD + d], 1);
    }
}

// 3. single-block fused colsum + scan + in-place offsets (+ final psrs/dense)
__global__ __launch_bounds__(1024) void k_prefix(int useH2, int nbFixed, int nchFix,
                                                 int modeM, int finalMode,
                                                 float* __restrict__ psrs) {
    __shared__ int ws[32];
    __shared__ int stot[4096];
    int* hist = useH2 ? g_hist2 : g_hist;
    int nb = finalMode ? (g_nC + 1) : nbFixed;
    int nch = modeM ? ((g_M + 1023) >> 10) : nchFix;
    int tid = threadIdx.x;
    int carry = 0;
    #pragma unroll
    for (int j = 0; j < 4; j++) {
        int b = j * 1024 + tid;
        int v = 0;
        if (b < nb)
            for (int c = 0; c < nch; c++) v += hist[c * NBPAD + b];
        stot[b] = v;
        int ex = blkscan_excl(v, tid, ws);
        int run = carry + ex;
        if (b < nb) {
            for (int c = 0; c < nch; c++) {
                int tmp = hist[c * NBPAD + b];
                hist[c * NBPAD + b] = run;
                run += tmp;
            }
        }
        carry += ws[31];
    }
    if (finalMode) {
        int carry2 = 0;
        #pragma unroll
        for (int j = 0; j < 4; j++) {
            int b = j * 1024 + tid;
            int v = (b < nb) ? stot[b] : 0;
            int occ = (b < nb && v > 0) ? 1 : 0;
            int exo = blkscan_excl(occ, tid, ws);
            int dr = carry2 + exo;
            if (b < nb) {
                g_dense[b] = dr;
                if (occ) psrs[dr] = (float)hist[b];   // hist[chunk0][b] == start[b]
            }
            carry2 += ws[31];
        }
        if (tid == 0) psrs[0] = 0.0f;
    }
}

// 4/6. stable radix scatter (spin ranks); optional fused next-pass histogram
__global__ __launch_bounds__(1024) void k_scatterR(int srcSel, int shift, int nb,
                                                   int useH2, int fuse) {
    int M = g_M;
    if ((blockIdx.x << 10) >= M) return;
    __shared__ int cnt[4096];
    __shared__ int s_turn;
    const uint64_t* in = srcSel ? g_keyB : g_keyA;
    uint64_t* out = srcSel ? g_keyA : g_keyB;
    int* hist = useH2 ? g_hist2 : g_hist;
    int tid = threadIdx.x;
    for (int b = tid; b < nb; b += 1024) cnt[b] = 0;
    if (tid == 0) s_turn = 0;
    int t = blockIdx.x * 1024 + tid;
    bool valid = t < M;
    uint64_t k = 0; int d = 0;
    if (valid) { k = in[t]; d = (int)((k >> shift) & (uint64_t)(nb - 1)); }
    __syncthreads();
    int rank = stable_rank_spin(d, valid, tid, cnt, &s_turn);
    if (valid) {
        int pos = hist[blockIdx.x * NBPAD + d] + rank;
        out[pos] = k;
        if (fuse) {
            int d2 = (int)((k >> 33) & 2047u);
            atomicAdd(&g_hist2[(pos >> 10) * NBPAD + d2], 1);
        }
    }
}

// 7. greedy NMS (single block) + cpoint rank map in tail
#define GS_SCP   0
#define GS_NXT   32768
#define GS_HEAD  40960
#define GS_CHX   51616
#define GS_CHY   55712
#define GS_CHZ   59808
#define GS_CHSEG 63904
#define GS_CHIDX 68000
#define GS_SALV  72096
#define GREEDY_SMEM 72320

__global__ __launch_bounds__(1024) void k_greedy(const float* __restrict__ cc,
                                                 const int* __restrict__ rs, int ns) {
    extern __shared__ char sm[];
    float4*   scp   = (float4*)(sm + GS_SCP);
    int*      nxt   = (int*)   (sm + GS_NXT);
    int*      head  = (int*)   (sm + GS_HEAD);
    float*    chx   = (float*) (sm + GS_CHX);
    float*    chy   = (float*) (sm + GS_CHY);
    float*    chz   = (float*) (sm + GS_CHZ);
    int*      chseg = (int*)   (sm + GS_CHSEG);
    int*      chidx = (int*)   (sm + GS_CHIDX);
    unsigned* salv  = (unsigned*)(sm + GS_SALV);
    __shared__ int snC;
    __shared__ int sbound[8];
    int tid = threadIdx.x;
    int lane = tid & 31, w = tid >> 5;
    for (int c = tid; c < GCELLS; c += 1024) head[c] = -1;
    if (tid == 0) snC = 0;
    int nsb = ns - 2;
    if (tid < nsb) sbound[tid] = rs[tid + 1];
    __syncthreads();

    int M = g_M;
    int nchunks = (M + CHUNK - 1) / CHUNK;
    for (int ch = 0; ch < nchunks; ch++) {
        int t = ch * CHUNK + tid;
        bool valid = t < M;
        float x = 1e30f, y = 1e30f, z = 1e30f;
        int seg = -1, oi = 0;
        if (valid) {
            oi = (int)(g_keyA[t] & IDXMASK);
            x = cc[3 * oi]; y = cc[3 * oi + 1]; z = cc[3 * oi + 2];
            seg = 0;
            for (int j = 0; j < nsb; j++) seg += (oi >= sbound[j]);
        }
        chx[tid] = x; chy[tid] = y; chz[tid] = z; chseg[tid] = seg; chidx[tid] = oi;

        // filter against existing cpoints (27-cell walk)
        bool hit = false;
        if (valid) {
            int cix = (int)floorf((x + GHALF) * CINV);
            int ciy = (int)floorf((y + GHALF) * CINV);
            int ciz = (int)floorf((z + GHALF) * CINV);
            #pragma unroll
            for (int dz = -1; dz <= 1; dz++) {
                int zz = min(GD - 1, max(0, ciz + dz));
                #pragma unroll
                for (int dy = -1; dy <= 1; dy++) {
                    int yy = min(GD - 1, max(0, ciy + dy));
                    #pragma unroll
                    for (int dx = -1; dx <= 1; dx++) {
                        int xx = min(GD - 1, max(0, cix + dx));
                        int c = head[((seg * GD + zz) * GD + yy) * GD + xx];
                        while (c >= 0 && !hit) {
                            float4 p = scp[c];
                            if (dist2(x, y, z, p.x, p.y, p.z) <= RAD2) hit = true;
                            c = nxt[c];
                        }
                    }
                }
            }
        }
        bool pending = valid && !hit;
        unsigned bal = __ballot_sync(0xffffffffu, pending);
        if (lane == 0) salv[w] = bal;
        __syncthreads();

        // warp-0 resolves: accept pendings in index order, kill in-radius later pendings
        if (w == 0) {
            unsigned wL = salv[lane];
            int nC = snC;
            while (true) {
                int cand = wL ? (lane * 32 + __ffs(wL) - 1) : 2048;
                #pragma unroll
                for (int o = 16; o; o >>= 1)
                    cand = min(cand, __shfl_xor_sync(0xffffffffu, cand, o));
                if (cand >= 2048) break;
                int j = cand;
                if (lane == (j >> 5)) wL &= ~(1u << (j & 31));
                float sx = chx[j], sy = chy[j], sz = chz[j];
                int sseg = chseg[j];
                if (nC < MAXCG) {
                    if (lane == 0) {
                        scp[nC] = make_float4(sx, sy, sz, __int_as_float(chidx[j]));
                        int cell = cell_of(sx, sy, sz, sseg);
                        nxt[nC] = head[cell]; head[cell] = nC;
                    }
                    nC++;
                }
                unsigned rem = wL;
                while (rem) {
                    int b = __ffs(rem) - 1; rem &= rem - 1;
                    int jj = lane * 32 + b;
                    if (chseg[jj] == sseg &&
                        dist2(chx[jj], chy[jj], chz[jj], sx, sy, sz) <= RAD2)
                        wL &= ~(1u << b);
                }
            }
            if (lane == 0) snC = nC;
        }
        __syncthreads();
    }

    int nC = snC;
    for (int e = tid; e < nC; e += 1024) {
        float4 p = scp[e];
        g_cp[e] = p;
        g_nxtG[e] = nxt[e];
        int myidx = __float_as_int(p.w);
        int cnt = 1;
        for (int e2 = 0; e2 < nC; e2++)
            cnt += (__float_as_int(scp[e2].w) < myidx);
        g_cpid2bin[e] = cnt;          // 1-based bin (bin 0 = unassigned)
    }
    for (int c = tid; c < GCELLS; c += 1024) g_headG[c] = head[c];
    if (tid == 0) g_nC = nC;
}

// 8. per-point assignment (min greedy rank within radius) + fused final histogram
#define P2_SCP  0
#define P2_NXT  32768
#define P2_HEAD 40960
#define P2_C2B  51616
#define P2_HIST 59808
#define P2_SMEM 68032

__global__ __launch_bounds__(1024) void k_phase2(const float* __restrict__ cc,
                                                 const int* __restrict__ rs, int ns,
                                                 int n, float* __restrict__ asso_out) {
    extern __shared__ char sm[];
    float4* scp  = (float4*)(sm + P2_SCP);
    int*    nxt  = (int*)(sm + P2_NXT);
    int*    head = (int*)(sm + P2_HEAD);
    int*    c2b  = (int*)(sm + P2_C2B);
    int*    hist = (int*)(sm + P2_HIST);
    __shared__ int sbound[8];
    __shared__ int s_nC;
    int tid = threadIdx.x;
    if (tid == 0) s_nC = g_nC;
    int nsb = ns - 2;
    if (tid < nsb) sbound[tid] = rs[tid + 1];
    __syncthreads();
    int nC = s_nC;
    int nb = nC + 1;
    for (int c = tid; c < nC; c += 1024) {
        scp[c] = g_cp[c]; nxt[c] = g_nxtG[c]; c2b[c] = g_cpid2bin[c];
    }
    for (int c = tid; c < GCELLS; c += 1024) head[c] = g_headG[c];
    for (int b = tid; b < nb; b += 1024) hist[b] = 0;
    __syncthreads();

    int i = blockIdx.x * 1024 + tid;
    if (i < n) {
        float x = cc[3 * i], y = cc[3 * i + 1], z = cc[3 * i + 2];
        int seg = 0;
        for (int j = 0; j < nsb; j++) seg += (i >= sbound[j]);
        int cix = (int)floorf((x + GHALF) * CINV);
        int ciy = (int)floorf((y + GHALF) * CINV);
        int ciz = (int)floorf((z + GHALF) * CINV);
        int best = 0x7fffffff;
        #pragma unroll
        for (int dz = -1; dz <= 1; dz++) {
            int zz = min(GD - 1, max(0, ciz + dz));
            #pragma unroll
            for (int dy = -1; dy <= 1; dy++) {
                int yy = min(GD - 1, max(0, ciy + dy));
                #pragma unroll
                for (int dx = -1; dx <= 1; dx++) {
                    int xx = min(GD - 1, max(0, cix + dx));
                    int c = head[((seg * GD + zz) * GD + yy) * GD + xx];
                    while (c >= 0) {
                        float4 p = scp[c];
                        if (c < best && dist2(x, y, z, p.x, p.y, p.z) <= RAD2) best = c;
                        c = nxt[c];
                    }
                }
            }
        }
        int bin, assov;
        if (best == 0x7fffffff) { bin = 0; assov = -1; }
        else { bin = c2b[best]; assov = __float_as_int(scp[best].w); }
        asso_out[i] = (float)assov;
        g_g[i] = bin;
        atomicAdd(&hist[bin], 1);
    }
    __syncthreads();
    for (int b = tid; b < nb; b += 1024) g_hist[blockIdx.x * NBPAD + b] = hist[b];
}

// 10. final stable scatter (spin ranks)
__global__ __launch_bounds__(1024) void k_scatterF(int n, float* __restrict__ sids,
                                                   float* __restrict__ belongs) {
    __shared__ int cnt[4096];
    __shared__ int s_turn;
    int nb = g_nC + 1;
    int tid = threadIdx.x;
    for (int b = tid; b < nb; b += 1024) cnt[b] = 0;
    if (tid == 0) s_turn = 0;
    int t = blockIdx.x * 1024 + tid;
    bool valid = t < n;
    int d = valid ? g_g[t] : 0;
    __syncthreads();
    int rank = stable_rank_spin(d, valid, tid, cnt, &s_turn);
    if (valid) {
        int pos = g_hist[blockIdx.x * NBPAD + d] + rank;
        g_pos[t] = pos;
        sids[pos] = (float)t;
        belongs[pos] = (float)g_dense[d];
    }
}

// 11. permute data rows
__global__ __launch_bounds__(512) void k_copy(const float* __restrict__ data,
                                              float* __restrict__ sdata, int n, int F) {
    int warp = (blockIdx.x * blockDim.x + threadIdx.x) >> 5;
    int lane = threadIdx.x & 31;
    if (warp >= n) return;
    int pos = g_pos[warp];
    const float4* src = (const float4*)(data + (size_t)warp * F);
    float4* dst = (float4*)(sdata + (size_t)pos * F);
    int nf4 = F >> 2;
    for (int k = lane; k < nf4; k += 32) dst[k] = src[k];
}

// ---------------- host launcher ----------------
extern "C" void kernel_launch(void* const* d_in, const int* in_sizes, int n_in,
                              void* d_out, int out_size) {
    const float* data  = (const float*)d_in[0];
    const float* cc    = (const float*)d_in[1];
    const float* betas = (const float*)d_in[2];
    const int*   rs    = (const int*)d_in[3];
    int N = in_sizes[2];
    int F = in_sizes[0] / N;
    int ns = in_sizes[3];

    float* out     = (float*)d_out;
    float* sdata   = out;
    float* psrs    = out + (size_t)N * F;
    float* sids    = psrs + (N + 1);
    float* asso    = sids + N;
    float* belongs = asso + N;

    int nch = (N + CHUNK - 1) / CHUNK;

    cudaFuncSetAttribute(k_greedy, cudaFuncAttributeMaxDynamicSharedMemorySize, GREEDY_SMEM);
    cudaFuncSetAttribute(k_phase2, cudaFuncAttributeMaxDynamicSharedMemorySize, P2_SMEM);

    k_candcount<<<nch, 1024>>>(betas, N, psrs);
    k_candscatter<<<nch, 1024>>>(betas, N);
    k_prefix<<<1, 1024>>>(0, 4096, 0, 1, 0, psrs);            // pass1 offsets
    k_scatterR<<<nch, 1024>>>(0, 21, 4096, 0, 1);             // A->B, fuse hist2
    k_prefix<<<1, 1024>>>(1, 2048, 0, 1, 0, psrs);            // pass2 offsets
    k_scatterR<<<nch, 1024>>>(1, 33, 2048, 1, 0);             // B->A
    k_greedy<<<1, 1024, GREEDY_SMEM>>>(cc, rs, ns);
    k_phase2<<<nch, 1024, P2_SMEM>>>(cc, rs, ns, N, asso);    // + final hist
    k_prefix<<<1, 1024>>>(0, 0, nch, 0, 1, psrs);             // final offsets + psrs/dense
    k_scatterF<<<nch, 1024>>>(N, sids, belongs);
    k_copy<<<(N + 15) / 16, 512>>>(data, sdata, N, F);
}

// round 8
// speedup vs baseline: 1.4660x; 1.4660x over previous
#include <cuda_runtime.h>
#include <cstdint>

// ---------------- constants ----------------
#define MAXN    262144
#define MAXCH   256
#define IDXBITS 21
#define IDXMASK ((1u<<IDXBITS)-1u)
#define RAD2    2.25f
#define MINBETA 0.8f

#define GD       11
#define GHALF    8.25f
#define CINV     0.666f
#define SEGCELLS (GD*GD*GD)      // 1331
#define GCELLS   (2*SEGCELLS)
#define HALFC    1024
#define MAXCG    2048
#define MAXSEG   2

// ---------------- device scratch ----------------
static __device__ uint64_t g_keyA[MAXN];
static __device__ uint64_t g_keyB[MAXN];
static __device__ uint32_t g_pk1[MAXN];
static __device__ uint32_t g_pk2[MAXN];
static __device__ int      g_rhc1[MAXCH*256];
static __device__ int      g_rhc2[MAXCH*256];
static __device__ int      g_rhc3[MAXCH*256];
static __device__ int      g_rp1 [MAXCH*256];
static __device__ int      g_rp2 [MAXCH*16];
static __device__ int      g_total[2304];
static __device__ int      g_dense[2304];
static __device__ int      g_ccnt[MAXCH];
static __device__ int      g_coff[MAXCH];
static __device__ int      g_done;
static __device__ int      g_done2;
static __device__ float4   g_cp[MAXCG];
static __device__ int      g_headG[GCELLS];
static __device__ int      g_nxtG[MAXCG];
static __device__ int      g_c2b[MAXCG];
static __device__ int      g_segCnt[MAXSEG];
static __device__ int      g_pos[MAXN];
static __device__ int      g_M;
static __device__ int      g_nCtot;

// ---------------- helpers ----------------
__device__ __forceinline__ int blkscan_excl(int v, int tid, int* ws) {
    __syncthreads();
    int lane = tid & 31, w = tid >> 5;
    int inc = v;
    #pragma unroll
    for (int o = 1; o < 32; o <<= 1) {
        int u = __shfl_up_sync(0xffffffffu, inc, o);
        if (lane >= o) inc += u;
    }
    if (lane == 31) ws[w] = inc;
    __syncthreads();
    if (tid < 32) {
        int s = ws[tid];
        #pragma unroll
        for (int o = 1; o < 32; o <<= 1) {
            int u = __shfl_up_sync(0xffffffffu, s, o);
            if (lane >= o) s += u;
        }
        ws[tid] = s;
    }
    __syncthreads();
    return (w ? ws[w - 1] : 0) + inc - v;
}

__device__ __forceinline__ float dist2(float ax, float ay, float az,
                                       float bx, float by, float bz) {
    float dx = ax - bx, dy = ay - by, dz = az - bz;
    return fmaf(dz, dz, fmaf(dy, dy, dx * dx));   // matches XLA fma chain
}

__device__ __forceinline__ int cell1(float v) {
    int c = (int)floorf((v + GHALF) * CINV);
    return c < 0 ? 0 : (c > GD - 1 ? GD - 1 : c);
}

// multisplit: stable rank + global position for (chunk, digit) ordering.
// hist: per-chunk digit counts [nch][NB]. Returns final global position, or -1.
// Rank within digit = scanned(d,w) - scanned(d,0)  (per-digit row base subtracted).
template<int NB>
__device__ __forceinline__ int msplit(const int* __restrict__ hist, int nch, int myc,
                                      int d, bool valid, int tid,
                                      int* base, int* pwh, int* ws) {
    for (int i = tid; i < NB * 32; i += 1024) pwh[i] = 0;
    int tot = 0, part = 0;
    if (tid < NB) {
        for (int c = 0; c < nch; c++) {
            int v = hist[c * NB + tid];
            part += (c < myc) ? v : 0;
            tot += v;
        }
    }
    int start = blkscan_excl(tid < NB ? tot : 0, tid, ws);  // syncs cover pwh zeroing
    if (tid < NB) base[tid] = start + part;
    int lane = tid & 31, w = tid >> 5;
    unsigned mm = __match_any_sync(0xffffffffu, valid ? d : (0x01000000 | lane));
    int lower = __popc(mm & ((1u << lane) - 1u));
    if (valid && lower == 0) pwh[d * 32 + w] = __popc(mm);
    __syncthreads();
    constexpr int PER = (NB * 32 + 1023) / 1024;
    int loc[PER], s = 0;
    #pragma unroll
    for (int j = 0; j < PER; j++) {
        int idx = tid * PER + j;
        loc[j] = (idx < NB * 32) ? pwh[idx] : 0;
        s += loc[j];
    }
    int ex = blkscan_excl(s, tid, ws);
    int run = ex;
    #pragma unroll
    for (int j = 0; j < PER; j++) {
        int idx = tid * PER + j;
        if (idx < NB * 32) { pwh[idx] = run; run += loc[j]; }
    }
    __syncthreads();
    return valid ? (base[d] + (pwh[d * 32 + w] - pwh[d * 32]) + lower) : -1;
}

// ---------------- kernels ----------------
// 1. zero hist scratch, init psrs, count candidates; last block scans -> g_M
__global__ __launch_bounds__(1024) void k_candcount(const float* __restrict__ betas, int n,
                                                    float* __restrict__ psrs) {
    int gsz = gridDim.x;
    int gt = blockIdx.x * 1024 + threadIdx.x;
    int stride = gsz * 1024;
    for (int i = gt; i < MAXCH * 256; i += stride) {
        g_rhc1[i] = 0; g_rhc2[i] = 0; g_rhc3[i] = 0;
    }
    for (int i = gt; i < MAXCH * 16; i += stride) g_rp2[i] = 0;
    for (int i = gt; i < 2304; i += stride) g_total[i] = 0;
    if (gt <= n) psrs[gt] = (float)n;
    int pred = (gt < n) && (betas[gt] >= MINBETA);
    int cnt = __syncthreads_count(pred);
    if (threadIdx.x == 0) {
        g_ccnt[blockIdx.x] = cnt;
        __threadfence();
        if (atomicAdd(&g_done, 1) == gsz - 1) {
            int s = 0;
            for (int c = 0; c < gsz; c++) { g_coff[c] = s; s += g_ccnt[c]; }
            g_M = s;
            g_done = 0;
        }
    }
}

// 2. compact candidate keys + fused pass-1 hist (shift 21)
__global__ __launch_bounds__(1024) void k_candscatter(const float* __restrict__ betas, int n) {
    __shared__ int ws[32];
    int tid = threadIdx.x;
    int t = blockIdx.x * 1024 + tid;
    int pred = (t < n) && (betas[t] >= MINBETA);
    int lr = blkscan_excl(pred, tid, ws);
    if (pred) {
        unsigned bits = __float_as_uint(betas[t]);
        uint64_t m = (~bits) & 0x7FFFFFu;
        uint64_t key = (m << IDXBITS) | (unsigned)t;
        int dest = g_coff[blockIdx.x] + lr;
        g_keyA[dest] = key;
        int d = (int)((key >> 21) & 255u);
        atomicAdd(&g_rhc1[(dest >> 10) * 256 + d], 1);
    }
}

// 3-5. candidate radix pass (8-bit multisplit); selectors pick arrays
__global__ __launch_bounds__(1024) void k_scatC(int srcSel, int histSel, int shift,
                                                int shiftnext) {
    __shared__ int base[256];
    __shared__ int pwh[8192];
    __shared__ int ws[32];
    int M = g_M;
    int myc = blockIdx.x;
    if (myc * 1024 >= M) return;
    int nch = (M + 1023) >> 10;
    const uint64_t* in = srcSel ? g_keyB : g_keyA;
    uint64_t* out = srcSel ? g_keyA : g_keyB;
    const int* hist = (histSel == 0) ? g_rhc1 : (histSel == 1 ? g_rhc2 : g_rhc3);
    int* nexthist = (histSel == 0) ? g_rhc2 : g_rhc3;
    int tid = threadIdx.x;
    int t = myc * 1024 + tid;
    bool valid = t < M;
    uint64_t k = valid ? in[t] : 0;
    int d = (int)((k >> shift) & 255u);
    int pos = msplit<256>(hist, nch, myc, d, valid, tid, base, pwh, ws);
    if (valid) {
        out[pos] = k;
        if (shiftnext >= 0) {
            int d2 = (int)((k >> shiftnext) & 255u);
            atomicAdd(&nexthist[(pos >> 10) * 256 + d2], 1);
        }
    }
}

// 6. greedy NMS: one block per segment; last block computes c2b map
__global__ __launch_bounds__(1024) void k_greedy(const float* __restrict__ cc,
                                                 const int* __restrict__ rs, int ns) {
    __shared__ float4   scp[HALFC];
    __shared__ int      nxt[HALFC];
    __shared__ int      head[SEGCELLS];
    __shared__ float    chx[1024], chy[1024], chz[1024];
    __shared__ int      chidx[1024];
    __shared__ unsigned salv[32];
    __shared__ int      snC;
    __shared__ int      sbound[8];
    __shared__ int      s_last;
    int tid = threadIdx.x, lane = tid & 31, w = tid >> 5;
    int myseg = blockIdx.x;
    int nseg = gridDim.x;
    for (int c = tid; c < SEGCELLS; c += 1024) head[c] = -1;
    if (tid == 0) snC = 0;
    int nsb = ns - 2;
    if (tid < nsb) sbound[tid] = rs[tid + 1];
    __syncthreads();

    int M = g_M;
    int nchunks = (M + 1023) >> 10;
    for (int ch = 0; ch < nchunks; ch++) {
        int t = ch * 1024 + tid;
        bool valid = t < M;
        float x = 1e30f, y = 1e30f, z = 1e30f;
        int oi = 0;
        if (valid) {
            oi = (int)(g_keyB[t] & IDXMASK);
            int seg = 0;
            for (int j = 0; j < nsb; j++) seg += (oi >= sbound[j]);
            valid = (seg == myseg);
            if (valid) { x = cc[3*oi]; y = cc[3*oi+1]; z = cc[3*oi+2]; }
        }
        chx[tid] = x; chy[tid] = y; chz[tid] = z; chidx[tid] = oi;

        bool hit = false;
        if (valid) {
            int cix = (int)floorf((x + GHALF) * CINV);
            int ciy = (int)floorf((y + GHALF) * CINV);
            int ciz = (int)floorf((z + GHALF) * CINV);
            #pragma unroll
            for (int dz = -1; dz <= 1; dz++) {
                int zz = min(GD - 1, max(0, ciz + dz));
                #pragma unroll
                for (int dy = -1; dy <= 1; dy++) {
                    int yy = min(GD - 1, max(0, ciy + dy));
                    #pragma unroll
                    for (int dx = -1; dx <= 1; dx++) {
                        int xx = min(GD - 1, max(0, cix + dx));
                        int c = head[(zz * GD + yy) * GD + xx];
                        while (c >= 0 && !hit) {
                            float4 p = scp[c];
                            if (dist2(x, y, z, p.x, p.y, p.z) <= RAD2) hit = true;
                            c = nxt[c];
                        }
                    }
                }
            }
        }
        bool pending = valid && !hit;
        unsigned bal = __ballot_sync(0xffffffffu, pending);
        if (lane == 0) salv[w] = bal;
        __syncthreads();

        if (w == 0) {
            unsigned wL = salv[lane];
            int nC = snC;
            while (true) {
                int cand = wL ? (lane * 32 + __ffs(wL) - 1) : 2048;
                #pragma unroll
                for (int o = 16; o; o >>= 1)
                    cand = min(cand, __shfl_xor_sync(0xffffffffu, cand, o));
                if (cand >= 2048) break;
                int j = cand;
                if (lane == (j >> 5)) wL &= ~(1u << (j & 31));
                float sx = chx[j], sy = chy[j], sz = chz[j];
                if (nC < HALFC) {
                    if (lane == 0) {
                        scp[nC] = make_float4(sx, sy, sz, __int_as_float(chidx[j]));
                        int cell = (cell1(sz) * GD + cell1(sy)) * GD + cell1(sx);
                        nxt[nC] = head[cell]; head[cell] = nC;
                    }
                    nC++;
                }
                unsigned rem = wL;
                while (rem) {
                    int b = __ffs(rem) - 1; rem &= rem - 1;
                    int jj = lane * 32 + b;
                    if (dist2(chx[jj], chy[jj], chz[jj], sx, sy, sz) <= RAD2)
                        wL &= ~(1u << b);
                }
            }
            if (lane == 0) snC = nC;
        }
        __syncthreads();
    }

    int nC = snC;
    int off = myseg * HALFC;
    for (int e = tid; e < nC; e += 1024) {
        g_cp[off + e] = scp[e];
        g_nxtG[off + e] = nxt[e] < 0 ? -1 : nxt[e] + off;
    }
    for (int c = tid; c < SEGCELLS; c += 1024)
        g_headG[myseg * SEGCELLS + c] = head[c] < 0 ? -1 : head[c] + off;
    __syncthreads();                      // all global stores done before publish
    if (tid == 0) {
        g_segCnt[myseg] = nC;
        __threadfence();
        int prev = atomicAdd(&g_done2, 1);
        s_last = (prev == nseg - 1) ? 1 : 0;
        if (s_last) g_done2 = 0;
    }
    __syncthreads();
    if (s_last) {
        __threadfence();
        int ntot = 0;
        for (int s = 0; s < nseg; s++) ntot += g_segCnt[s];
        if (tid == 0) g_nCtot = ntot;
        for (int s = 0; s < nseg; s++) {
            int cs = g_segCnt[s];
            for (int e = tid; e < cs; e += 1024) {
                int myidx = __float_as_int(g_cp[s * HALFC + e].w);
                int cnt = 1;
                for (int s2 = 0; s2 < nseg; s2++) {
                    int cs2 = g_segCnt[s2];
                    for (int e2 = 0; e2 < cs2; e2++)
                        cnt += (__float_as_int(g_cp[s2 * HALFC + e2].w) < myidx);
                }
                g_c2b[s * HALFC + e] = cnt;
            }
        }
    }
}

// 7. per-point assignment + pk1 + per-chunk hists + global totals
#define P2_SCP  0
#define P2_NXT  32768
#define P2_HEAD 40960
#define P2_C2B  51616
#define P2_HIST 59808
#define P2_SMEM 68032

__global__ __launch_bounds__(1024) void k_phase2(const float* __restrict__ cc,
                                                 const int* __restrict__ rs, int ns,
                                                 int n, float* __restrict__ asso_out) {
    extern __shared__ char sm[];
    float4* scp  = (float4*)(sm + P2_SCP);
    int*    nxt  = (int*)(sm + P2_NXT);
    int*    head = (int*)(sm + P2_HEAD);
    int*    c2b  = (int*)(sm + P2_C2B);
    int*    hist = (int*)(sm + P2_HIST);
    __shared__ int sbound[8];
    __shared__ int segcnt[MAXSEG];
    __shared__ int s_ntot;
    int tid = threadIdx.x;
    int nseg = ns - 1;
    if (tid == 0) s_ntot = g_nCtot;
    if (tid < nseg) segcnt[tid] = g_segCnt[tid];
    int nsb = ns - 2;
    if (tid < nsb) sbound[tid] = rs[tid + 1];
    __syncthreads();
    int nb = s_ntot + 1;
    for (int s = 0; s < nseg; s++) {
        int cs = segcnt[s];
        for (int e = tid; e < cs; e += 1024) {
            int g = s * HALFC + e;
            scp[g] = g_cp[g]; nxt[g] = g_nxtG[g]; c2b[g] = g_c2b[g];
        }
    }
    for (int c = tid; c < GCELLS; c += 1024) head[c] = g_headG[c];
    for (int b = tid; b < nb; b += 1024) hist[b] = 0;
    __syncthreads();

    int i = blockIdx.x * 1024 + tid;
    if (i < n) {
        float x = cc[3*i], y = cc[3*i+1], z = cc[3*i+2];
        int seg = 0;
        for (int j = 0; j < nsb; j++) seg += (i >= sbound[j]);
        int cix = (int)floorf((x + GHALF) * CINV);
        int ciy = (int)floorf((y + GHALF) * CINV);
        int ciz = (int)floorf((z + GHALF) * CINV);
        int best = 0x7fffffff;
        #pragma unroll
        for (int dz = -1; dz <= 1; dz++) {
            int zz = min(GD - 1, max(0, ciz + dz));
            #pragma unroll
            for (int dy = -1; dy <= 1; dy++) {
                int yy = min(GD - 1, max(0, ciy + dy));
                #pragma unroll
                for (int dx = -1; dx <= 1; dx++) {
                    int xx = min(GD - 1, max(0, cix + dx));
                    int c = head[(seg * SEGCELLS) + (zz * GD + yy) * GD + xx];
                    while (c >= 0) {
                        float4 p = scp[c];
                        if (c < best && dist2(x, y, z, p.x, p.y, p.z) <= RAD2) best = c;
                        c = nxt[c];
                    }
                }
            }
        }
        int bin, assov;
        if (best == 0x7fffffff) { bin = 0; assov = -1; }
        else { bin = c2b[best]; assov = __float_as_int(scp[best].w); }
        asso_out[i] = (float)assov;
        g_pk1[i] = ((uint32_t)bin << 18) | (uint32_t)i;
        atomicAdd(&hist[bin], 1);
    }
    __syncthreads();
    for (int b = tid; b < nb; b += 1024) {
        int h = hist[b];
        if (h) atomicAdd(&g_total[b], h);
    }
    for (int d = tid; d < 256; d += 1024) {
        int s = 0;
        for (int b = d; b < nb; b += 256) s += hist[b];
        g_rp1[blockIdx.x * 256 + d] = s;
    }
}

// 8. psrs + dense from totals (single block)
__global__ __launch_bounds__(1024) void k_pfxF(float* __restrict__ psrs) {
    __shared__ int ws[32];
    int nb = g_nCtot + 1;
    int tid = threadIdx.x;
    int carry = 0, carry2 = 0;
    #pragma unroll
    for (int j = 0; j < 3; j++) {
        int b = j * 1024 + tid;
        int v = (b < nb) ? g_total[b] : 0;
        int ex = blkscan_excl(v, tid, ws);
        int startb = carry + ex;
        int tb = ws[31];
        int occ = (b < nb && v > 0) ? 1 : 0;
        int exo = blkscan_excl(occ, tid, ws);
        int dr = carry2 + exo;
        if (b < nb) {
            g_dense[b] = dr;
            if (occ) psrs[dr] = (float)startb;
        }
        carry += tb;
        carry2 += ws[31];
    }
    if (tid == 0) psrs[0] = 0.0f;
}

// 9. point sort pass 1 (bits 18..25), pk1 -> pk2, fused 4-bit hist
__global__ __launch_bounds__(1024) void k_scatP1(int n, int nch) {
    __shared__ int base[256];
    __shared__ int pwh[8192];
    __shared__ int ws[32];
    int myc = blockIdx.x;
    int tid = threadIdx.x;
    int t = myc * 1024 + tid;
    bool valid = t < n;
    uint32_t k = valid ? g_pk1[t] : 0;
    int d = (int)((k >> 18) & 255u);
    int pos = msplit<256>(g_rp1, nch, myc, d, valid, tid, base, pwh, ws);
    if (valid) {
        g_pk2[pos] = k;
        int d2 = (int)((k >> 26) & 15u);
        atomicAdd(&g_rp2[(pos >> 10) * 16 + d2], 1);
    }
}

// 10. point sort pass 2 (bits 26..29) + final outputs
__global__ __launch_bounds__(1024) void k_scatP2(int n, int nch,
                                                 float* __restrict__ sids,
                                                 float* __restrict__ belongs) {
    __shared__ int base[16];
    __shared__ int pwh[512];
    __shared__ int ws[32];
    int myc = blockIdx.x;
    int tid = threadIdx.x;
    int t = myc * 1024 + tid;
    bool valid = t < n;
    uint32_t k = valid ? g_pk2[t] : 0;
    int d = (int)((k >> 26) & 15u);
    int pos = msplit<16>(g_rp2, nch, myc, d, valid, tid, base, pwh, ws);
    if (valid) {
        int i = (int)(k & 0x3FFFFu);
        int bin = (int)(k >> 18);
        sids[pos] = (float)i;
        belongs[pos] = (float)g_dense[bin];
        g_pos[i] = pos;
    }
}

// 11. permute data rows
__global__ __launch_bounds__(512) void k_copy(const float* __restrict__ data,
                                              float* __restrict__ sdata, int n, int F) {
    int warp = (blockIdx.x * blockDim.x + threadIdx.x) >> 5;
    int lane = threadIdx.x & 31;
    if (warp >= n) return;
    int pos = g_pos[warp];
    const float4* src = (const float4*)(data + (size_t)warp * F);
    float4* dst = (float4*)(sdata + (size_t)pos * F);
    int nf4 = F >> 2;
    for (int k = lane; k < nf4; k += 32) dst[k] = src[k];
}

// ---------------- host launcher ----------------
extern "C" void kernel_launch(void* const* d_in, const int* in_sizes, int n_in,
                              void* d_out, int out_size) {
    const float* data  = (const float*)d_in[0];
    const float* cc    = (const float*)d_in[1];
    const float* betas = (const float*)d_in[2];
    const int*   rs    = (const int*)d_in[3];
    int N = in_sizes[2];
    int F = in_sizes[0] / N;
    int ns = in_sizes[3];
    int nseg = ns - 1;

    float* out     = (float*)d_out;
    float* sdata   = out;
    float* psrs    = out + (size_t)N * F;
    float* sids    = psrs + (N + 1);
    float* asso    = sids + N;
    float* belongs = asso + N;

    int nch = (N + 1023) / 1024;

    cudaFuncSetAttribute(k_phase2, cudaFuncAttributeMaxDynamicSharedMemorySize, P2_SMEM);

    k_candcount<<<nch, 1024>>>(betas, N, psrs);
    k_candscatter<<<nch, 1024>>>(betas, N);
    k_scatC<<<nch, 1024>>>(0, 0, 21, 29);     // A->B
    k_scatC<<<nch, 1024>>>(1, 1, 29, 37);     // B->A
    k_scatC<<<nch, 1024>>>(0, 2, 37, -1);     // A->B  (sorted in B)
    k_greedy<<<nseg, 1024>>>(cc, rs, ns);
    k_phase2<<<nch, 1024, P2_SMEM>>>(cc, rs, ns, N, asso);
    k_pfxF<<<1, 1024>>>(psrs);
    k_scatP1<<<nch, 1024>>>(N, nch);
    k_scatP2<<<nch, 1024>>>(N, nch, sids, belongs);
    k_copy<<<(N + 15) / 16, 512>>>(data, sdata, N, F);
}

// round 11
// speedup vs baseline: 1.8298x; 1.2481x over previous
#include <cuda_runtime.h>
#include <cstdint>

// ---------------- constants ----------------
#define MAXN    262144
#define MAXCH   256
#define IDXBITS 21
#define IDXMASK ((1u<<IDXBITS)-1u)
#define RAD2    2.25f
#define MINBETA 0.8f

#define GD       11
#define GHALF    8.25f
#define CINV     0.666f
#define SEGCELLS (GD*GD*GD)      // 1331
#define GCELLS   (2*SEGCELLS)
#define HALFC    1024
#define MAXCG    2048
#define MAXSEG   2

// ---------------- device scratch ----------------
static __device__ uint64_t g_keyA[MAXN];
static __device__ float4   g_cand[MAXN];       // sorted candidates: x,y,z, w=(seg<<18|idx)
static __device__ uint32_t g_pk1[MAXN];
static __device__ uint32_t g_pk2[MAXN];
static __device__ int      g_bcnt[256];
static __device__ int      g_bcur[256];
static __device__ int      g_bstart[256];
static __device__ int      g_rp1 [MAXCH*256];
static __device__ int      g_rp2 [MAXCH*16];
static __device__ int      g_total[2304];
static __device__ int      g_dense[2304];
static __device__ int      g_done;
static __device__ int      g_done2;
static __device__ float4   g_cp[MAXCG];
static __device__ int      g_headG[GCELLS];
static __device__ int      g_nxtG[MAXCG];
static __device__ int      g_c2b[MAXCG];
static __device__ int      g_segCnt[MAXSEG];
static __device__ int      g_pos[MAXN];
static __device__ int      g_M;
static __device__ int      g_nCtot;

// ---------------- helpers ----------------
__device__ __forceinline__ int blkscan_excl(int v, int tid, int* ws) {
    __syncthreads();
    int lane = tid & 31, w = tid >> 5;
    int inc = v;
    #pragma unroll
    for (int o = 1; o < 32; o <<= 1) {
        int u = __shfl_up_sync(0xffffffffu, inc, o);
        if (lane >= o) inc += u;
    }
    if (lane == 31) ws[w] = inc;
    __syncthreads();
    if (tid < 32) {
        int s = ws[tid];
        #pragma unroll
        for (int o = 1; o < 32; o <<= 1) {
            int u = __shfl_up_sync(0xffffffffu, s, o);
            if (lane >= o) s += u;
        }
        ws[tid] = s;
    }
    __syncthreads();
    return (w ? ws[w - 1] : 0) + inc - v;
}

__device__ __forceinline__ float dist2(float ax, float ay, float az,
                                       float bx, float by, float bz) {
    float dx = ax - bx, dy = ay - by, dz = az - bz;
    return fmaf(dz, dz, fmaf(dy, dy, dx * dx));   // matches XLA fma chain
}

__device__ __forceinline__ int cell1(float v) {
    int c = (int)floorf((v + GHALF) * CINV);
    return c < 0 ? 0 : (c > GD - 1 ? GD - 1 : c);
}

// multisplit: stable rank + global position for (chunk, digit) ordering.
template<int NB>
__device__ __forceinline__ int msplit(const int* __restrict__ hist, int nch, int myc,
                                      int d, bool valid, int tid,
                                      int* base, int* pwh, int* ws) {
    for (int i = tid; i < NB * 32; i += 1024) pwh[i] = 0;
    int tot = 0, part = 0;
    if (tid < NB) {
        for (int c = 0; c < nch; c++) {
            int v = hist[c * NB + tid];
            part += (c < myc) ? v : 0;
            tot += v;
        }
    }
    int start = blkscan_excl(tid < NB ? tot : 0, tid, ws);
    if (tid < NB) base[tid] = start + part;
    int lane = tid & 31, w = tid >> 5;
    unsigned mm = __match_any_sync(0xffffffffu, valid ? d : (0x01000000 | lane));
    int lower = __popc(mm & ((1u << lane) - 1u));
    if (valid && lower == 0) pwh[d * 32 + w] = __popc(mm);
    __syncthreads();
    constexpr int PER = (NB * 32 + 1023) / 1024;
    int loc[PER], s = 0;
    #pragma unroll
    for (int j = 0; j < PER; j++) {
        int idx = tid * PER + j;
        loc[j] = (idx < NB * 32) ? pwh[idx] : 0;
        s += loc[j];
    }
    int ex = blkscan_excl(s, tid, ws);
    int run = ex;
    #pragma unroll
    for (int j = 0; j < PER; j++) {
        int idx = tid * PER + j;
        if (idx < NB * 32) { pwh[idx] = run; run += loc[j]; }
    }
    __syncthreads();
    return valid ? (base[d] + (pwh[d * 32 + w] - pwh[d * 32]) + lower) : -1;
}

// ---------------- kernels ----------------
// 1. psrs init + bucket histogram; last block computes bucket starts + g_M
__global__ __launch_bounds__(1024) void k_candcount(const float* __restrict__ betas, int n,
                                                    float* __restrict__ psrs) {
    __shared__ int lh[256];
    __shared__ int ws[32];
    __shared__ int s_last;
    int tid = threadIdx.x;
    if (tid < 256) lh[tid] = 0;
    __syncthreads();
    int gt = blockIdx.x * 1024 + tid;
    if (gt <= n) psrs[gt] = (float)n;
    if (gt < n) {
        float b = betas[gt];
        if (b >= MINBETA) {
            unsigned m = (~__float_as_uint(b)) & 0x7FFFFFu;
            atomicAdd(&lh[m >> 15], 1);
        }
    }
    __syncthreads();
    if (tid < 256 && lh[tid]) atomicAdd(&g_bcnt[tid], lh[tid]);
    __threadfence();
    if (tid == 0) {
        int prev = atomicAdd(&g_done, 1);
        s_last = (prev == (int)gridDim.x - 1) ? 1 : 0;
        if (s_last) g_done = 0;
    }
    __syncthreads();
    if (s_last) {
        __threadfence();
        int v = (tid < 256) ? g_bcnt[tid] : 0;
        int ex = blkscan_excl(v, tid, ws);
        if (tid < 256) g_bstart[tid] = ex;
        if (tid == 255) g_M = ex + v;
    }
}

// 2. scatter candidate keys into buckets (intra-bucket order arbitrary)
__global__ __launch_bounds__(1024) void k_candscatter(const float* __restrict__ betas, int n) {
    __shared__ int lh[256];
    __shared__ int lbase[256];
    int tid = threadIdx.x;
    if (tid < 256) lh[tid] = 0;
    __syncthreads();
    int gt = blockIdx.x * 1024 + tid;
    bool pred = false; int d = 0, slot = 0; uint64_t key = 0;
    if (gt < n) {
        float b = betas[gt];
        if (b >= MINBETA) {
            pred = true;
            unsigned m = (~__float_as_uint(b)) & 0x7FFFFFu;
            d = (int)(m >> 15);
            key = ((uint64_t)m << IDXBITS) | (unsigned)gt;
            slot = atomicAdd(&lh[d], 1);
        }
    }
    __syncthreads();
    if (tid < 256 && lh[tid]) lbase[tid] = atomicAdd(&g_bcur[tid], lh[tid]);
    __syncthreads();
    if (pred) g_keyA[g_bstart[d] + lbase[d] + slot] = key;
}

// 3. exact in-bucket sort + gather coords; emits sorted g_cand
__global__ __launch_bounds__(1024) void k_bucketsort(const float* __restrict__ cc,
                                                     const int* __restrict__ rs, int ns) {
    __shared__ uint64_t skey[2048];
    __shared__ int sbound[8];
    int b = blockIdx.x;
    int B = g_bcnt[b];
    if (B == 0) return;
    int start = g_bstart[b];
    int tid = threadIdx.x;
    int nsb = ns - 2;
    if (tid < nsb) sbound[tid] = rs[tid + 1];
    if (B <= 2048) {
        for (int e = tid; e < B; e += 1024) skey[e] = g_keyA[start + e];
        __syncthreads();
        for (int e = tid; e < B; e += 1024) {
            uint64_t k = skey[e];
            int r = 0;
            for (int j = 0; j < B; j++) r += (skey[j] < k);
            int idx = (int)(k & IDXMASK);
            int seg = 0;
            for (int j = 0; j < nsb; j++) seg += (idx >= sbound[j]);
            float x = cc[3*idx], y = cc[3*idx+1], z = cc[3*idx+2];
            g_cand[start + r] = make_float4(x, y, z, __int_as_float((seg << 18) | idx));
        }
    } else {                                  // fallback: exact, global scan
        __syncthreads();
        for (int e = tid; e < B; e += 1024) {
            uint64_t k = g_keyA[start + e];
            int r = 0;
            for (int j = 0; j < B; j++) r += (g_keyA[start + j] < k);
            int idx = (int)(k & IDXMASK);
            int seg = 0;
            for (int j = 0; j < nsb; j++) seg += (idx >= sbound[j]);
            float x = cc[3*idx], y = cc[3*idx+1], z = cc[3*idx+2];
            g_cand[start + r] = make_float4(x, y, z, __int_as_float((seg << 18) | idx));
        }
    }
}

// 4. greedy NMS: one block per segment; last block computes c2b map
__global__ __launch_bounds__(1024) void k_greedy() {
    __shared__ float4   scp[HALFC];
    __shared__ int      nxt[HALFC];
    __shared__ int      head[SEGCELLS];
    __shared__ float    chx[1024], chy[1024], chz[1024];
    __shared__ int      chidx[1024];
    __shared__ unsigned salv[32];
    __shared__ int      snC;
    __shared__ int      s_last;
    int tid = threadIdx.x, lane = tid & 31, w = tid >> 5;
    int myseg = blockIdx.x;
    int nseg = gridDim.x;
    for (int c = tid; c < SEGCELLS; c += 1024) head[c] = -1;
    if (tid == 0) snC = 0;
    __syncthreads();

    int M = g_M;
    int nchunks = (M + 1023) >> 10;
    for (int ch = 0; ch < nchunks; ch++) {
        int t = ch * 1024 + tid;
        bool valid = t < M;
        float x = 1e30f, y = 1e30f, z = 1e30f;
        int oi = 0;
        if (valid) {
            float4 f4 = g_cand[t];
            int si = __float_as_int(f4.w);
            valid = ((si >> 18) == myseg);
            oi = si & 0x3FFFF;
            if (valid) { x = f4.x; y = f4.y; z = f4.z; }
        }
        chx[tid] = x; chy[tid] = y; chz[tid] = z; chidx[tid] = oi;

        bool hit = false;
        if (valid) {
            int cix = (int)floorf((x + GHALF) * CINV);
            int ciy = (int)floorf((y + GHALF) * CINV);
            int ciz = (int)floorf((z + GHALF) * CINV);
            #pragma unroll
            for (int dz = -1; dz <= 1; dz++) {
                int zz = min(GD - 1, max(0, ciz + dz));
                #pragma unroll
                for (int dy = -1; dy <= 1; dy++) {
                    int yy = min(GD - 1, max(0, ciy + dy));
                    #pragma unroll
                    for (int dx = -1; dx <= 1; dx++) {
                        int xx = min(GD - 1, max(0, cix + dx));
                        int c = head[(zz * GD + yy) * GD + xx];
                        while (c >= 0 && !hit) {
                            float4 p = scp[c];
                            if (dist2(x, y, z, p.x, p.y, p.z) <= RAD2) hit = true;
                            c = nxt[c];
                        }
                    }
                }
            }
        }
        bool pending = valid && !hit;
        unsigned bal = __ballot_sync(0xffffffffu, pending);
        if (lane == 0) salv[w] = bal;
        __syncthreads();

        if (w == 0) {
            unsigned wL = salv[lane];
            int nC = snC;
            while (true) {
                int cand = wL ? (lane * 32 + __ffs(wL) - 1) : 2048;
                #pragma unroll
                for (int o = 16; o; o >>= 1)
                    cand = min(cand, __shfl_xor_sync(0xffffffffu, cand, o));
                if (cand >= 2048) break;
                int j = cand;
                if (lane == (j >> 5)) wL &= ~(1u << (j & 31));
                float sx = chx[j], sy = chy[j], sz = chz[j];
                if (nC < HALFC) {
                    if (lane == 0) {
                        scp[nC] = make_float4(sx, sy, sz, __int_as_float(chidx[j]));
                        int cell = (cell1(sz) * GD + cell1(sy)) * GD + cell1(sx);
                        nxt[nC] = head[cell]; head[cell] = nC;
                    }
                    nC++;
                }
                unsigned rem = wL;
                while (rem) {
                    int b = __ffs(rem) - 1; rem &= rem - 1;
                    int jj = lane * 32 + b;
                    if (dist2(chx[jj], chy[jj], chz[jj], sx, sy, sz) <= RAD2)
                        wL &= ~(1u << b);
                }
            }
            if (lane == 0) snC = nC;
        }
        __syncthreads();
    }

    int nC = snC;
    int off = myseg * HALFC;
    for (int e = tid; e < nC; e += 1024) {
        g_cp[off + e] = scp[e];
        g_nxtG[off + e] = nxt[e] < 0 ? -1 : nxt[e] + off;
    }
    for (int c = tid; c < SEGCELLS; c += 1024)
        g_headG[myseg * SEGCELLS + c] = head[c] < 0 ? -1 : head[c] + off;
    __syncthreads();
    if (tid == 0) {
        g_segCnt[myseg] = nC;
        __threadfence();
        int prev = atomicAdd(&g_done2, 1);
        s_last = (prev == nseg - 1) ? 1 : 0;
        if (s_last) g_done2 = 0;
    }
    __syncthreads();
    if (s_last) {
        __threadfence();
        int ntot = 0;
        for (int s = 0; s < nseg; s++) ntot += g_segCnt[s];
        if (tid == 0) g_nCtot = ntot;
        for (int s = 0; s < nseg; s++) {
            int cs = g_segCnt[s];
            for (int e = tid; e < cs; e += 1024) {
                int myidx = __float_as_int(g_cp[s * HALFC + e].w);
                int cnt = 1;
                for (int s2 = 0; s2 < nseg; s2++) {
                    int cs2 = g_segCnt[s2];
                    for (int e2 = 0; e2 < cs2; e2++)
                        cnt += (__float_as_int(g_cp[s2 * HALFC + e2].w) < myidx);
                }
                g_c2b[s * HALFC + e] = cnt;
            }
        }
    }
}

// 5. per-point assignment + pk1 + per-chunk hists + global totals
#define P2_SCP  0
#define P2_NXT  32768
#define P2_HEAD 40960
#define P2_C2B  51616
#define P2_HIST 59808
#define P2_SMEM 68032

__global__ __launch_bounds__(1024) void k_phase2(const float* __restrict__ cc,
                                                 const int* __restrict__ rs, int ns,
                                                 int n, float* __restrict__ asso_out) {
    extern __shared__ char sm[];
    float4* scp  = (float4*)(sm + P2_SCP);
    int*    nxt  = (int*)(sm + P2_NXT);
    int*    head = (int*)(sm + P2_HEAD);
    int*    c2b  = (int*)(sm + P2_C2B);
    int*    hist = (int*)(sm + P2_HIST);
    __shared__ int sbound[8];
    __shared__ int segcnt[MAXSEG];
    __shared__ int s_ntot;
    int tid = threadIdx.x;
    int nseg = ns - 1;
    if (tid == 0) s_ntot = g_nCtot;
    if (tid < nseg) segcnt[tid] = g_segCnt[tid];
    int nsb = ns - 2;
    if (tid < nsb) sbound[tid] = rs[tid + 1];
    __syncthreads();
    int nb = s_ntot + 1;
    for (int s = 0; s < nseg; s++) {
        int cs = segcnt[s];
        for (int e = tid; e < cs; e += 1024) {
            int g = s * HALFC + e;
            scp[g] = g_cp[g]; nxt[g] = g_nxtG[g]; c2b[g] = g_c2b[g];
        }
    }
    for (int c = tid; c < GCELLS; c += 1024) head[c] = g_headG[c];
    for (int b = tid; b < nb; b += 1024) hist[b] = 0;
    __syncthreads();

    int i = blockIdx.x * 1024 + tid;
    if (i < n) {
        float x = cc[3*i], y = cc[3*i+1], z = cc[3*i+2];
        int seg = 0;
        for (int j = 0; j < nsb; j++) seg += (i >= sbound[j]);
        int cix = (int)floorf((x + GHALF) * CINV);
        int ciy = (int)floorf((y + GHALF) * CINV);
        int ciz = (int)floorf((z + GHALF) * CINV);
        int best = 0x7fffffff;
        #pragma unroll
        for (int dz = -1; dz <= 1; dz++) {
            int zz = min(GD - 1, max(0, ciz + dz));
            #pragma unroll
            for (int dy = -1; dy <= 1; dy++) {
                int yy = min(GD - 1, max(0, ciy + dy));
                #pragma unroll
                for (int dx = -1; dx <= 1; dx++) {
                    int xx = min(GD - 1, max(0, cix + dx));
                    int c = head[(seg * SEGCELLS) + (zz * GD + yy) * GD + xx];
                    while (c >= 0) {
                        float4 p = scp[c];
                        if (c < best && dist2(x, y, z, p.x, p.y, p.z) <= RAD2) best = c;
                        c = nxt[c];
                    }
                }
            }
        }
        int bin, assov;
        if (best == 0x7fffffff) { bin = 0; assov = -1; }
        else { bin = c2b[best]; assov = __float_as_int(scp[best].w); }
        asso_out[i] = (float)assov;
        g_pk1[i] = ((uint32_t)bin << 18) | (uint32_t)i;
        atomicAdd(&hist[bin], 1);
    }
    __syncthreads();
    for (int b = tid; b < nb; b += 1024) {
        int h = hist[b];
        if (h) atomicAdd(&g_total[b], h);
    }
    for (int d = tid; d < 256; d += 1024) {
        int s = 0;
        for (int b = d; b < nb; b += 256) s += hist[b];
        g_rp1[blockIdx.x * 256 + d] = s;
    }
}

// 6. psrs + dense from totals (single block)
__global__ __launch_bounds__(1024) void k_pfxF(float* __restrict__ psrs) {
    __shared__ int ws[32];
    int nb = g_nCtot + 1;
    int tid = threadIdx.x;
    int carry = 0, carry2 = 0;
    #pragma unroll
    for (int j = 0; j < 3; j++) {
        int b = j * 1024 + tid;
        int v = (b < nb) ? g_total[b] : 0;
        int ex = blkscan_excl(v, tid, ws);
        int startb = carry + ex;
        int tb = ws[31];
        int occ = (b < nb && v > 0) ? 1 : 0;
        int exo = blkscan_excl(occ, tid, ws);
        int dr = carry2 + exo;
        if (b < nb) {
            g_dense[b] = dr;
            if (occ) psrs[dr] = (float)startb;
        }
        carry += tb;
        carry2 += ws[31];
    }
    if (tid == 0) psrs[0] = 0.0f;
}

// 7. point sort pass 1 (bits 18..25), pk1 -> pk2, fused 4-bit hist
__global__ __launch_bounds__(1024) void k_scatP1(int n, int nch) {
    __shared__ int base[256];
    __shared__ int pwh[8192];
    __shared__ int ws[32];
    int myc = blockIdx.x;
    int tid = threadIdx.x;
    int t = myc * 1024 + tid;
    bool valid = t < n;
    uint32_t k = valid ? g_pk1[t] : 0;
    int d = (int)((k >> 18) & 255u);
    int pos = msplit<256>(g_rp1, nch, myc, d, valid, tid, base, pwh, ws);
    if (valid) {
        g_pk2[pos] = k;
        int d2 = (int)((k >> 26) & 15u);
        atomicAdd(&g_rp2[(pos >> 10) * 16 + d2], 1);
    }
}

// 8. point sort pass 2 (bits 26..29) + final outputs
__global__ __launch_bounds__(1024) void k_scatP2(int n, int nch,
                                                 float* __restrict__ sids,
                                                 float* __restrict__ belongs) {
    __shared__ int base[16];
    __shared__ int pwh[512];
    __shared__ int ws[32];
    int myc = blockIdx.x;
    int tid = threadIdx.x;
    int t = myc * 1024 + tid;
    bool valid = t < n;
    uint32_t k = valid ? g_pk2[t] : 0;
    int d = (int)((k >> 26) & 15u);
    int pos = msplit<16>(g_rp2, nch, myc, d, valid, tid, base, pwh, ws);
    if (valid) {
        int i = (int)(k & 0x3FFFFu);
        int bin = (int)(k >> 18);
        sids[pos] = (float)i;
        belongs[pos] = (float)g_dense[bin];
        g_pos[i] = pos;
    }
}

// 9. permute data rows; block 0 re-zeroes atomic scratch for next graph replay
__global__ __launch_bounds__(512) void k_copy(const float* __restrict__ data,
                                              float* __restrict__ sdata, int n, int F) {
    if (blockIdx.x == 0) {
        int tid = threadIdx.x;
        for (int i = tid; i < 256; i += 512) { g_bcnt[i] = 0; g_bcur[i] = 0; }
        for (int i = tid; i < MAXCH * 16; i += 512) g_rp2[i] = 0;
        for (int i = tid; i < 2304; i += 512) g_total[i] = 0;
    }
    int warp = (blockIdx.x * blockDim.x + threadIdx.x) >> 5;
    int lane = threadIdx.x & 31;
    if (warp >= n) return;
    int pos = g_pos[warp];
    const float4* src = (const float4*)(data + (size_t)warp * F);
    float4* dst = (float4*)(sdata + (size_t)pos * F);
    int nf4 = F >> 2;
    for (int k = lane; k < nf4; k += 32) dst[k] = src[k];
}

// ---------------- host launcher ----------------
extern "C" void kernel_launch(void* const* d_in, const int* in_sizes, int n_in,
                              void* d_out, int out_size) {
    const float* data  = (const float*)d_in[0];
    const float* cc    = (const float*)d_in[1];
    const float* betas = (const float*)d_in[2];
    const int*   rs    = (const int*)d_in[3];
    int N = in_sizes[2];
    int F = in_sizes[0] / N;
    int ns = in_sizes[3];
    int nseg = ns - 1;

    float* out     = (float*)d_out;
    float* sdata   = out;
    float* psrs    = out + (size_t)N * F;
    float* sids    = psrs + (N + 1);
    float* asso    = sids + N;
    float* belongs = asso + N;

    int nch = (N + 1023) / 1024;

    cudaFuncSetAttribute(k_phase2, cudaFuncAttributeMaxDynamicSharedMemorySize, P2_SMEM);

    k_candcount<<<nch, 1024>>>(betas, N, psrs);
    k_candscatter<<<nch, 1024>>>(betas, N);
    k_bucketsort<<<256, 1024>>>(cc, rs, ns);
    k_greedy<<<nseg, 1024>>>();
    k_phase2<<<nch, 1024, P2_SMEM>>>(cc, rs, ns, N, asso);
    k_pfxF<<<1, 1024>>>(psrs);
    k_scatP1<<<nch, 1024>>>(N, nch);
    k_scatP2<<<nch, 1024>>>(N, nch, sids, belongs);
    k_copy<<<(N + 15) / 16, 512>>>(data, sdata, N, F);
}